// round 14
// baseline (speedup 1.0000x reference)
#include <cuda_runtime.h>
#include <cstdint>

// Problem constants
#define BSZ 4096
#define DD  1024
#define CC  10000

// GEMM tiling (int8 mma.sync m16n8k32, s32 accumulate)
// 128x128x128B block, FOUR warps (2x2 grid of 64x64 warp tiles), 2 CTAs/SM.
#define BM 128
#define BN 128
#define BKB 128                   // K bytes (=elements) per stage
#define ROWB 144                  // padded row: 128B data + 16B pad (conflict-free)
#define NSTG 3
#define NKT (DD / BKB)            // 8
#define A_BYTES (BM * ROWB)       // 18432
#define B_BYTES (BN * ROWB)       // 18432
#define STG_BYTES (A_BYTES + B_BYTES)      // 36864
#define A_OFF(st) ((st) * STG_BYTES)
#define B_OFF(st) ((st) * STG_BYTES + A_BYTES)
#define SMEM_TOTAL (NSTG * STG_BYTES)      // 110592 (x2 CTA <= 227KB/SM)

// Scratch (device globals -- no allocation allowed)
__device__ float g_xx[BSZ];
__device__ float g_sx[BSZ];
__device__ float g_yy[10240];
__device__ float g_sy[10240];
__device__ float g_var2[10240];
__device__ float g_partial[BSZ];
__device__ __align__(16) signed char g_feati[(size_t)BSZ * DD];
__device__ __align__(16) signed char g_meansi[(size_t)CC * DD];

// ---------------------------------------------------------------------------
// helpers
// ---------------------------------------------------------------------------
__device__ __forceinline__ uint32_t smem_u32(const void* p) {
    return (uint32_t)__cvta_generic_to_shared(p);
}

__device__ __forceinline__ void cp16(uint32_t dst, const void* src, int src_sz) {
    asm volatile("cp.async.cg.shared.global [%0], [%1], 16, %2;\n"
                 :: "r"(dst), "l"(src), "r"(src_sz));
}

__device__ __forceinline__ void ldmx4(uint32_t* r, uint32_t addr) {
    asm volatile("ldmatrix.sync.aligned.m8n8.x4.shared.b16 {%0,%1,%2,%3}, [%4];"
                 : "=r"(r[0]), "=r"(r[1]), "=r"(r[2]), "=r"(r[3]) : "r"(addr));
}

__device__ __forceinline__ int q8(float x, float inv) {
    int v = __float2int_rn(x * inv);
    return max(-127, min(127, v));
}

// ---------------------------------------------------------------------------
// prep: feat -> int8 (per-row scale) + XX on QUANTIZED values + rowdiff
// ---------------------------------------------------------------------------
__global__ void k_prep_feat_diff(const float* __restrict__ feat,
                                 const int* __restrict__ labels,
                                 const float* __restrict__ means) {
    const int b = blockIdx.x;
    const int t = threadIdx.x;
    int lbl = labels[b];
    if (lbl < 0) lbl = 0;
    if (lbl >= CC) lbl = CC - 1;
    const float4* f4 = (const float4*)(feat + (size_t)b * DD);
    const float4* m4 = (const float4*)(means + (size_t)lbl * DD);
    float4 v0 = f4[2 * t], v1 = f4[2 * t + 1];
    float4 m0 = m4[2 * t], m1 = m4[2 * t + 1];

    float d;
    {
        float dx = v0.x - m0.x, dy = v0.y - m0.y, dz = v0.z - m0.z, dw = v0.w - m0.w;
        d = dx * dx + dy * dy + dz * dz + dw * dw;
        dx = v1.x - m1.x; dy = v1.y - m1.y; dz = v1.z - m1.z; dw = v1.w - m1.w;
        d += dx * dx + dy * dy + dz * dz + dw * dw;
    }
    float amax = fmaxf(fmaxf(fmaxf(fabsf(v0.x), fabsf(v0.y)), fmaxf(fabsf(v0.z), fabsf(v0.w))),
                       fmaxf(fmaxf(fabsf(v1.x), fabsf(v1.y)), fmaxf(fabsf(v1.z), fabsf(v1.w))));

    __shared__ float shm[4];
    #pragma unroll
    for (int o = 16; o; o >>= 1) amax = fmaxf(amax, __shfl_xor_sync(0xffffffffu, amax, o));
    if ((t & 31) == 0) shm[t >> 5] = amax;
    __syncthreads();
    amax = fmaxf(fmaxf(shm[0], shm[1]), fmaxf(shm[2], shm[3]));

    const float s   = amax * (1.0f / 127.0f);
    const float inv = (amax > 0.0f) ? 127.0f / amax : 0.0f;

    int q0 = q8(v0.x, inv), q1 = q8(v0.y, inv), q2 = q8(v0.z, inv), q3 = q8(v0.w, inv);
    int q4 = q8(v1.x, inv), q5 = q8(v1.y, inv), q6 = q8(v1.z, inv), q7 = q8(v1.w, inv);
    int p0 = (q0 & 255) | ((q1 & 255) << 8) | ((q2 & 255) << 16) | ((q3 & 255) << 24);
    int p1 = (q4 & 255) | ((q5 & 255) << 8) | ((q6 & 255) << 16) | ((q7 & 255) << 24);
    ((int2*)(g_feati + (size_t)b * DD))[t] = make_int2(p0, p1);

    int qsq = q0 * q0 + q1 * q1 + q2 * q2 + q3 * q3
            + q4 * q4 + q5 * q5 + q6 * q6 + q7 * q7;

    __shared__ int   shq[4];
    __shared__ float shd[4];
    #pragma unroll
    for (int o = 16; o; o >>= 1) {
        qsq += __shfl_xor_sync(0xffffffffu, qsq, o);
        d   += __shfl_xor_sync(0xffffffffu, d, o);
    }
    if ((t & 31) == 0) { shq[t >> 5] = qsq; shd[t >> 5] = d; }
    __syncthreads();
    if (t == 0) {
        int qs = shq[0] + shq[1] + shq[2] + shq[3];
        g_xx[b] = s * s * (float)qs;
        g_sx[b] = s;
        g_partial[b] = shd[0] + shd[1] + shd[2] + shd[3];
    }
}

// ---------------------------------------------------------------------------
// prep: means -> int8 + YY on quantized + var^2
// ---------------------------------------------------------------------------
__global__ void k_prep_means(const float* __restrict__ means,
                             const float* __restrict__ variance) {
    const int c = blockIdx.x;
    const int t = threadIdx.x;
    const float4* f4 = (const float4*)(means + (size_t)c * DD);
    float4 v0 = f4[2 * t], v1 = f4[2 * t + 1];

    float amax = fmaxf(fmaxf(fmaxf(fabsf(v0.x), fabsf(v0.y)), fmaxf(fabsf(v0.z), fabsf(v0.w))),
                       fmaxf(fmaxf(fabsf(v1.x), fabsf(v1.y)), fmaxf(fabsf(v1.z), fabsf(v1.w))));
    __shared__ float shm[4];
    #pragma unroll
    for (int o = 16; o; o >>= 1) amax = fmaxf(amax, __shfl_xor_sync(0xffffffffu, amax, o));
    if ((t & 31) == 0) shm[t >> 5] = amax;
    __syncthreads();
    amax = fmaxf(fmaxf(shm[0], shm[1]), fmaxf(shm[2], shm[3]));

    const float s   = amax * (1.0f / 127.0f);
    const float inv = (amax > 0.0f) ? 127.0f / amax : 0.0f;

    int q0 = q8(v0.x, inv), q1 = q8(v0.y, inv), q2 = q8(v0.z, inv), q3 = q8(v0.w, inv);
    int q4 = q8(v1.x, inv), q5 = q8(v1.y, inv), q6 = q8(v1.z, inv), q7 = q8(v1.w, inv);
    int p0 = (q0 & 255) | ((q1 & 255) << 8) | ((q2 & 255) << 16) | ((q3 & 255) << 24);
    int p1 = (q4 & 255) | ((q5 & 255) << 8) | ((q6 & 255) << 16) | ((q7 & 255) << 24);
    ((int2*)(g_meansi + (size_t)c * DD))[t] = make_int2(p0, p1);

    int qsq = q0 * q0 + q1 * q1 + q2 * q2 + q3 * q3
            + q4 * q4 + q5 * q5 + q6 * q6 + q7 * q7;
    __shared__ int shq[4];
    #pragma unroll
    for (int o = 16; o; o >>= 1) qsq += __shfl_xor_sync(0xffffffffu, qsq, o);
    if ((t & 31) == 0) shq[t >> 5] = qsq;
    __syncthreads();
    if (t == 0) {
        int qs = shq[0] + shq[1] + shq[2] + shq[3];
        g_yy[c] = s * s * (float)qs;
        g_sy[c] = s;
        float v = variance[c];
        g_var2[c] = v * v;
    }
}

// ---------------------------------------------------------------------------
// means -> out copy
// ---------------------------------------------------------------------------
__global__ void k_copy(const float* __restrict__ src, float* __restrict__ dst) {
    size_t n = (size_t)CC * DD;
    for (size_t i = (size_t)blockIdx.x * blockDim.x + threadIdx.x; i < n;
         i += (size_t)gridDim.x * blockDim.x)
        dst[i] = src[i];
}

__global__ void k_reduce(float* __restrict__ out) {
    __shared__ float sh[1024];
    float s = 0.0f;
    for (int i = threadIdx.x; i < BSZ; i += 1024) s += g_partial[i];
    sh[threadIdx.x] = s;
    __syncthreads();
    for (int off = 512; off; off >>= 1) {
        if (threadIdx.x < off) sh[threadIdx.x] += sh[threadIdx.x + off];
        __syncthreads();
    }
    if (threadIdx.x == 0)
        out[0] = sh[0] * (0.01f * 0.5f / (float)BSZ);   // LAMBDA * 0.5 / B
}

// ---------------------------------------------------------------------------
// int8 GEMM: 128x128x128B, 128 threads (warp tile 64x64, 2x2), 2 CTAs/SM.
// ---------------------------------------------------------------------------
__device__ __forceinline__ void load_tile(uint32_t aB, uint32_t bB,
                                          int bm0, int bn0, int k0, int tid) {
    const int c  = tid & 7;        // 16B chunk within 128B row
    const int r0 = tid >> 3;       // 0..15
    #pragma unroll
    for (int rr = 0; rr < 8; rr++) {
        const int row = r0 + rr * 16;
        cp16(aB + row * ROWB + c * 16,
             g_feati + (size_t)(bm0 + row) * DD + k0 + c * 16, 16);
    }
    #pragma unroll
    for (int rr = 0; rr < 8; rr++) {
        const int row = r0 + rr * 16;
        const int br = bn0 + row;
        cp16(bB + row * ROWB + c * 16,
             g_meansi + (size_t)(br < CC ? br : 0) * DD + k0 + c * 16,
             br < CC ? 16 : 0);
    }
    asm volatile("cp.async.commit_group;\n" ::: "memory");
}

extern __shared__ char dsm[];

__global__ void __launch_bounds__(128, 2)
k_gemm(const int* __restrict__ labels, float* __restrict__ out) {
    const int tid  = threadIdx.x;
    const int lane = tid & 31;
    const int warp = tid >> 5;      // 0..3
    const int g  = lane >> 2;
    const int tg = lane & 3;
    const int wr = warp & 1;        // 2 warp-rows x 64
    const int wc = warp >> 1;       // 2 warp-cols x 64
    const int bm0 = blockIdx.y * BM;
    const int bn0 = blockIdx.x * BN;

    const uint32_t sb = smem_u32(dsm);

    const uint32_t aoff = (uint32_t)(wr * 64 + (lane & 15)) * ROWB + (lane >> 4) * 16;
    const uint32_t boff = (uint32_t)(wc * 64 + (lane & 7) + ((lane >> 4) << 3)) * ROWB
                        + ((lane >> 3) & 1) * 16;

    int acc[4][8][4];               // 4 m-frags x 8 n-frags x 4 = 128 regs
    #pragma unroll
    for (int i = 0; i < 4; i++)
        #pragma unroll
        for (int j = 0; j < 8; j++)
            #pragma unroll
            for (int r = 0; r < 4; r++) acc[i][j][r] = 0;

    // double-buffered fragments: 2*(4+4)*4 = 64 regs
    uint32_t af[2][4][4], bf[2][4][4];

    load_tile(sb + A_OFF(0), sb + B_OFF(0), bm0, bn0, 0 * BKB, tid);
    load_tile(sb + A_OFF(1), sb + B_OFF(1), bm0, bn0, 1 * BKB, tid);

    int st = 0;
    for (int kt = 0; kt < NKT; ++kt) {
        asm volatile("cp.async.wait_group 1;\n" ::: "memory");
        __syncthreads();

        const int kn = kt + 2;
        if (kn < NKT) {
            int sn = st + 2; if (sn >= NSTG) sn -= NSTG;
            load_tile(sb + A_OFF(sn), sb + B_OFF(sn), bm0, bn0, kn * BKB, tid);
        } else {
            asm volatile("cp.async.commit_group;\n" ::: "memory");
        }

        const uint32_t aT = sb + A_OFF(st) + aoff;
        const uint32_t bT = sb + B_OFF(st) + boff;

        // ks=0 fragments into buffer 0
        #pragma unroll
        for (int i = 0; i < 4; i++) ldmx4(af[0][i], aT + i * (16 * ROWB));
        #pragma unroll
        for (int jp = 0; jp < 4; jp++) ldmx4(bf[0][jp], bT + jp * (16 * ROWB));

        #pragma unroll
        for (int ks = 0; ks < 4; ++ks) {
            const int cur = ks & 1, nxt = cur ^ 1;
            if (ks < 3) {
                #pragma unroll
                for (int i = 0; i < 4; i++)
                    ldmx4(af[nxt][i], aT + i * (16 * ROWB) + (ks + 1) * 32);
                #pragma unroll
                for (int jp = 0; jp < 4; jp++)
                    ldmx4(bf[nxt][jp], bT + jp * (16 * ROWB) + (ks + 1) * 32);
            }
            #pragma unroll
            for (int i = 0; i < 4; i++)
                #pragma unroll
                for (int j = 0; j < 8; j++) {
                    const uint32_t b0 = bf[cur][j >> 1][(j & 1) * 2 + 0];
                    const uint32_t b1 = bf[cur][j >> 1][(j & 1) * 2 + 1];
                    asm volatile(
                        "mma.sync.aligned.m16n8k32.row.col.s32.s8.s8.s32 "
                        "{%0,%1,%2,%3}, {%4,%5,%6,%7}, {%8,%9}, {%0,%1,%2,%3};\n"
                        : "+r"(acc[i][j][0]), "+r"(acc[i][j][1]),
                          "+r"(acc[i][j][2]), "+r"(acc[i][j][3])
                        : "r"(af[cur][i][0]), "r"(af[cur][i][1]),
                          "r"(af[cur][i][2]), "r"(af[cur][i][3]),
                          "r"(b0), "r"(b1));
                }
        }
        if (++st == NSTG) st = 0;
    }

    // ---------------- fused epilogue ----------------
    const int rbase = bm0 + wr * 64;
    float xx[4][2], sxr[4][2];
    int lab[4][2];
    #pragma unroll
    for (int i = 0; i < 4; i++)
        #pragma unroll
        for (int h = 0; h < 2; h++) {
            int row = rbase + i * 16 + g + h * 8;
            xx[i][h]  = g_xx[row];
            sxr[i][h] = g_sx[row];
            lab[i][h] = labels[row];
        }

    const int cbase = bn0 + wc * 64;
    #pragma unroll
    for (int j = 0; j < 8; j++) {
        int c0 = cbase + j * 8 + tg * 2;
        if (c0 < CC) {
            float yy0 = g_yy[c0],   yy1 = g_yy[c0 + 1];
            float sy0 = g_sy[c0],   sy1 = g_sy[c0 + 1];
            float v0  = g_var2[c0], v1  = g_var2[c0 + 1];
            #pragma unroll
            for (int i = 0; i < 4; i++)
                #pragma unroll
                for (int h = 0; h < 2; h++) {
                    int row = rbase + i * 16 + g + h * 8;
                    float xy0 = sxr[i][h] * sy0 * (float)acc[i][j][h * 2 + 0];
                    float xy1 = sxr[i][h] * sy1 * (float)acc[i][j][h * 2 + 1];
                    float l0 = -0.5f * (xx[i][h] - 2.0f * xy0 + yy0) * v0;
                    float l1 = -0.5f * (xx[i][h] - 2.0f * xy1 + yy1) * v1;
                    if (lab[i][h] == c0)     l0 *= 1.1f;
                    if (lab[i][h] == c0 + 1) l1 *= 1.1f;
                    float2 st2; st2.x = l0; st2.y = l1;
                    *(float2*)(out + (size_t)row * CC + c0) = st2;
                }
        }
    }
}

// ---------------------------------------------------------------------------
extern "C" void kernel_launch(void* const* d_in, const int* in_sizes, int n_in,
                              void* d_out, int out_size) {
    const float* feat     = (const float*)d_in[0];
    const int*   labels   = (const int*)d_in[1];     // int32 (JAX x64 disabled)
    const float* means    = (const float*)d_in[2];
    const float* variance = (const float*)d_in[3];
    float* out = (float*)d_out;

    const long long logitsN = (long long)BSZ * CC;      // 40,960,000
    const long long meansN  = (long long)CC * DD;       // 10,240,000
    long long osz = (long long)out_size;
    const int do_copy = (osz >= logitsN + 1 + meansN) ? 1 : 0;
    const int do_loss = (osz >= logitsN + 1) ? 1 : 0;

    cudaFuncSetAttribute(k_gemm, cudaFuncAttributeMaxDynamicSharedMemorySize,
                         SMEM_TOTAL);

    static cudaStream_t sCopy = nullptr, sMeans = nullptr, sRed = nullptr;
    static cudaEvent_t eFork = nullptr, eFeat = nullptr, eMeans = nullptr,
                       eCopyD = nullptr, eRedD = nullptr;
    if (!sCopy) {
        cudaStreamCreateWithFlags(&sCopy,  cudaStreamNonBlocking);
        cudaStreamCreateWithFlags(&sMeans, cudaStreamNonBlocking);
        cudaStreamCreateWithFlags(&sRed,   cudaStreamNonBlocking);
        cudaEventCreateWithFlags(&eFork,  cudaEventDisableTiming);
        cudaEventCreateWithFlags(&eFeat,  cudaEventDisableTiming);
        cudaEventCreateWithFlags(&eMeans, cudaEventDisableTiming);
        cudaEventCreateWithFlags(&eCopyD, cudaEventDisableTiming);
        cudaEventCreateWithFlags(&eRedD,  cudaEventDisableTiming);
    }

    cudaEventRecord(eFork, 0);

    if (do_copy) {
        cudaStreamWaitEvent(sCopy, eFork, 0);
        k_copy<<<2048, 256, 0, sCopy>>>(means, out + logitsN + 1);
    }

    cudaStreamWaitEvent(sMeans, eFork, 0);
    k_prep_means<<<CC, 128, 0, sMeans>>>(means, variance);

    k_prep_feat_diff<<<BSZ, 128>>>(feat, labels, means);
    cudaEventRecord(eFeat, 0);

    if (do_loss) {
        cudaStreamWaitEvent(sRed, eFeat, 0);
        k_reduce<<<1, 1024, 0, sRed>>>(out + logitsN);
    }

    cudaEventRecord(eMeans, sMeans);
    cudaStreamWaitEvent(0, eMeans, 0);

    dim3 grid((CC + BN - 1) / BN, BSZ / BM);   // 79 x 32
    k_gemm<<<grid, 128, SMEM_TOTAL>>>(labels, out);

    if (do_copy) { cudaEventRecord(eCopyD, sCopy); cudaStreamWaitEvent(0, eCopyD, 0); }
    if (do_loss) { cudaEventRecord(eRedD,  sRed);  cudaStreamWaitEvent(0, eRedD, 0); }
}

// round 15
// speedup vs baseline: 1.0401x; 1.0401x over previous
#include <cuda_runtime.h>
#include <cstdint>

// Problem constants
#define BSZ 4096
#define DD  1024
#define CC  10000

// GEMM tiling (int8 mma.sync m16n8k32, s32 accumulate) -- round-12 winner
#define BM 128
#define BN 128
#define BKB 128                   // K bytes (=elements) per stage
#define ROWB 144                  // padded row: 128B data + 16B pad (conflict-free)
#define NSTG 3
#define NKT (DD / BKB)            // 8
#define A_BYTES (BM * ROWB)       // 18432
#define B_BYTES (BN * ROWB)       // 18432
#define STG_BYTES (A_BYTES + B_BYTES)      // 36864
#define A_OFF(st) ((st) * STG_BYTES)
#define B_OFF(st) ((st) * STG_BYTES + A_BYTES)
#define SMEM_TOTAL (NSTG * STG_BYTES)      // 110592 (x2 CTA <= 227KB/SM)

// Scratch (device globals -- no allocation allowed)
__device__ float g_xx[BSZ];
__device__ float g_sx[BSZ];
__device__ float g_yy[10240];
__device__ float g_sy[10240];
__device__ float g_var2[10240];
__device__ float g_partial[BSZ];
__device__ __align__(16) signed char g_feati[(size_t)BSZ * DD];
__device__ __align__(16) signed char g_meansi[(size_t)CC * DD];

// ---------------------------------------------------------------------------
// helpers
// ---------------------------------------------------------------------------
__device__ __forceinline__ uint32_t smem_u32(const void* p) {
    return (uint32_t)__cvta_generic_to_shared(p);
}

__device__ __forceinline__ void cp16(uint32_t dst, const void* src, int src_sz) {
    asm volatile("cp.async.cg.shared.global [%0], [%1], 16, %2;\n"
                 :: "r"(dst), "l"(src), "r"(src_sz));
}

__device__ __forceinline__ void ldmx4(uint32_t* r, uint32_t addr) {
    asm volatile("ldmatrix.sync.aligned.m8n8.x4.shared.b16 {%0,%1,%2,%3}, [%4];"
                 : "=r"(r[0]), "=r"(r[1]), "=r"(r[2]), "=r"(r[3]) : "r"(addr));
}

__device__ __forceinline__ int q8(float x, float inv) {
    int v = __float2int_rn(x * inv);
    return max(-127, min(127, v));
}

// ---------------------------------------------------------------------------
// prep: feat -> int8 (per-row scale) + XX on QUANTIZED values + rowdiff
// ---------------------------------------------------------------------------
__global__ void k_prep_feat_diff(const float* __restrict__ feat,
                                 const int* __restrict__ labels,
                                 const float* __restrict__ means) {
    const int b = blockIdx.x;
    const int t = threadIdx.x;
    int lbl = labels[b];
    if (lbl < 0) lbl = 0;
    if (lbl >= CC) lbl = CC - 1;
    const float4* f4 = (const float4*)(feat + (size_t)b * DD);
    const float4* m4 = (const float4*)(means + (size_t)lbl * DD);
    float4 v0 = f4[2 * t], v1 = f4[2 * t + 1];
    float4 m0 = m4[2 * t], m1 = m4[2 * t + 1];

    float d;
    {
        float dx = v0.x - m0.x, dy = v0.y - m0.y, dz = v0.z - m0.z, dw = v0.w - m0.w;
        d = dx * dx + dy * dy + dz * dz + dw * dw;
        dx = v1.x - m1.x; dy = v1.y - m1.y; dz = v1.z - m1.z; dw = v1.w - m1.w;
        d += dx * dx + dy * dy + dz * dz + dw * dw;
    }
    float amax = fmaxf(fmaxf(fmaxf(fabsf(v0.x), fabsf(v0.y)), fmaxf(fabsf(v0.z), fabsf(v0.w))),
                       fmaxf(fmaxf(fabsf(v1.x), fabsf(v1.y)), fmaxf(fabsf(v1.z), fabsf(v1.w))));

    __shared__ float shm[4];
    #pragma unroll
    for (int o = 16; o; o >>= 1) amax = fmaxf(amax, __shfl_xor_sync(0xffffffffu, amax, o));
    if ((t & 31) == 0) shm[t >> 5] = amax;
    __syncthreads();
    amax = fmaxf(fmaxf(shm[0], shm[1]), fmaxf(shm[2], shm[3]));

    const float s   = amax * (1.0f / 127.0f);
    const float inv = (amax > 0.0f) ? 127.0f / amax : 0.0f;

    int q0 = q8(v0.x, inv), q1 = q8(v0.y, inv), q2 = q8(v0.z, inv), q3 = q8(v0.w, inv);
    int q4 = q8(v1.x, inv), q5 = q8(v1.y, inv), q6 = q8(v1.z, inv), q7 = q8(v1.w, inv);
    int p0 = (q0 & 255) | ((q1 & 255) << 8) | ((q2 & 255) << 16) | ((q3 & 255) << 24);
    int p1 = (q4 & 255) | ((q5 & 255) << 8) | ((q6 & 255) << 16) | ((q7 & 255) << 24);
    ((int2*)(g_feati + (size_t)b * DD))[t] = make_int2(p0, p1);

    int qsq = q0 * q0 + q1 * q1 + q2 * q2 + q3 * q3
            + q4 * q4 + q5 * q5 + q6 * q6 + q7 * q7;

    __shared__ int   shq[4];
    __shared__ float shd[4];
    #pragma unroll
    for (int o = 16; o; o >>= 1) {
        qsq += __shfl_xor_sync(0xffffffffu, qsq, o);
        d   += __shfl_xor_sync(0xffffffffu, d, o);
    }
    if ((t & 31) == 0) { shq[t >> 5] = qsq; shd[t >> 5] = d; }
    __syncthreads();
    if (t == 0) {
        int qs = shq[0] + shq[1] + shq[2] + shq[3];
        g_xx[b] = s * s * (float)qs;
        g_sx[b] = s;
        g_partial[b] = shd[0] + shd[1] + shd[2] + shd[3];
    }
}

// ---------------------------------------------------------------------------
// prep: means -> int8 + YY on quantized + var^2
// ---------------------------------------------------------------------------
__global__ void k_prep_means(const float* __restrict__ means,
                             const float* __restrict__ variance) {
    const int c = blockIdx.x;
    const int t = threadIdx.x;
    const float4* f4 = (const float4*)(means + (size_t)c * DD);
    float4 v0 = f4[2 * t], v1 = f4[2 * t + 1];

    float amax = fmaxf(fmaxf(fmaxf(fabsf(v0.x), fabsf(v0.y)), fmaxf(fabsf(v0.z), fabsf(v0.w))),
                       fmaxf(fmaxf(fabsf(v1.x), fabsf(v1.y)), fmaxf(fabsf(v1.z), fabsf(v1.w))));
    __shared__ float shm[4];
    #pragma unroll
    for (int o = 16; o; o >>= 1) amax = fmaxf(amax, __shfl_xor_sync(0xffffffffu, amax, o));
    if ((t & 31) == 0) shm[t >> 5] = amax;
    __syncthreads();
    amax = fmaxf(fmaxf(shm[0], shm[1]), fmaxf(shm[2], shm[3]));

    const float s   = amax * (1.0f / 127.0f);
    const float inv = (amax > 0.0f) ? 127.0f / amax : 0.0f;

    int q0 = q8(v0.x, inv), q1 = q8(v0.y, inv), q2 = q8(v0.z, inv), q3 = q8(v0.w, inv);
    int q4 = q8(v1.x, inv), q5 = q8(v1.y, inv), q6 = q8(v1.z, inv), q7 = q8(v1.w, inv);
    int p0 = (q0 & 255) | ((q1 & 255) << 8) | ((q2 & 255) << 16) | ((q3 & 255) << 24);
    int p1 = (q4 & 255) | ((q5 & 255) << 8) | ((q6 & 255) << 16) | ((q7 & 255) << 24);
    ((int2*)(g_meansi + (size_t)c * DD))[t] = make_int2(p0, p1);

    int qsq = q0 * q0 + q1 * q1 + q2 * q2 + q3 * q3
            + q4 * q4 + q5 * q5 + q6 * q6 + q7 * q7;
    __shared__ int shq[4];
    #pragma unroll
    for (int o = 16; o; o >>= 1) qsq += __shfl_xor_sync(0xffffffffu, qsq, o);
    if ((t & 31) == 0) shq[t >> 5] = qsq;
    __syncthreads();
    if (t == 0) {
        int qs = shq[0] + shq[1] + shq[2] + shq[3];
        g_yy[c] = s * s * (float)qs;
        g_sy[c] = s;
        float v = variance[c];
        g_var2[c] = v * v;
    }
}

// ---------------------------------------------------------------------------
// means -> out copy: few fat grid-stride CTAs (backfills around the GEMM)
// ---------------------------------------------------------------------------
__global__ void k_copy(const float* __restrict__ src, float* __restrict__ dst) {
    size_t n = (size_t)CC * DD;
    for (size_t i = (size_t)blockIdx.x * blockDim.x + threadIdx.x; i < n;
         i += (size_t)gridDim.x * blockDim.x)
        dst[i] = src[i];
}

__global__ void k_reduce(float* __restrict__ out) {
    __shared__ float sh[1024];
    float s = 0.0f;
    for (int i = threadIdx.x; i < BSZ; i += 1024) s += g_partial[i];
    sh[threadIdx.x] = s;
    __syncthreads();
    for (int off = 512; off; off >>= 1) {
        if (threadIdx.x < off) sh[threadIdx.x] += sh[threadIdx.x + off];
        __syncthreads();
    }
    if (threadIdx.x == 0)
        out[0] = sh[0] * (0.01f * 0.5f / (float)BSZ);   // LAMBDA * 0.5 / B
}

// ---------------------------------------------------------------------------
// int8 GEMM (s32 accumulate) + fused epilogue. (byte-identical to R12 winner)
// ---------------------------------------------------------------------------
__device__ __forceinline__ void load_tile(uint32_t aB, uint32_t bB,
                                          int bm0, int bn0, int k0, int tid) {
    const int c  = tid & 7;
    const int r0 = tid >> 3;
    #pragma unroll
    for (int rr = 0; rr < 4; rr++) {
        const int row = r0 + rr * 32;
        cp16(aB + row * ROWB + c * 16,
             g_feati + (size_t)(bm0 + row) * DD + k0 + c * 16, 16);
    }
    #pragma unroll
    for (int rr = 0; rr < 4; rr++) {
        const int row = r0 + rr * 32;
        const int br = bn0 + row;
        cp16(bB + row * ROWB + c * 16,
             g_meansi + (size_t)(br < CC ? br : 0) * DD + k0 + c * 16,
             br < CC ? 16 : 0);
    }
    asm volatile("cp.async.commit_group;\n" ::: "memory");
}

extern __shared__ char dsm[];

__global__ void __launch_bounds__(256, 2)
k_gemm(const int* __restrict__ labels, float* __restrict__ out) {
    const int tid  = threadIdx.x;
    const int lane = tid & 31;
    const int warp = tid >> 5;
    const int g  = lane >> 2;
    const int tg = lane & 3;
    const int wr = warp & 1;
    const int wc = warp >> 1;
    const int bm0 = blockIdx.y * BM;
    const int bn0 = blockIdx.x * BN;

    const uint32_t sb = smem_u32(dsm);

    const uint32_t aoff = (uint32_t)(wr * 64 + (lane & 15)) * ROWB + (lane >> 4) * 16;
    const uint32_t boff = (uint32_t)(wc * 32 + (lane & 7) + ((lane >> 4) << 3)) * ROWB
                        + ((lane >> 3) & 1) * 16;

    int acc[4][4][4];
    #pragma unroll
    for (int i = 0; i < 4; i++)
        #pragma unroll
        for (int j = 0; j < 4; j++)
            #pragma unroll
            for (int r = 0; r < 4; r++) acc[i][j][r] = 0;

    load_tile(sb + A_OFF(0), sb + B_OFF(0), bm0, bn0, 0 * BKB, tid);
    load_tile(sb + A_OFF(1), sb + B_OFF(1), bm0, bn0, 1 * BKB, tid);

    int st = 0;
    for (int kt = 0; kt < NKT; ++kt) {
        asm volatile("cp.async.wait_group 1;\n" ::: "memory");
        __syncthreads();

        const int kn = kt + 2;
        if (kn < NKT) {
            int sn = st + 2; if (sn >= NSTG) sn -= NSTG;
            load_tile(sb + A_OFF(sn), sb + B_OFF(sn), bm0, bn0, kn * BKB, tid);
        } else {
            asm volatile("cp.async.commit_group;\n" ::: "memory");
        }

        const uint32_t aT = sb + A_OFF(st) + aoff;
        const uint32_t bT = sb + B_OFF(st) + boff;

        #pragma unroll
        for (int ks = 0; ks < 4; ++ks) {
            uint32_t af[4][4], bf[2][4];
            #pragma unroll
            for (int i = 0; i < 4; i++)
                ldmx4(af[i], aT + i * (16 * ROWB) + ks * 32);
            #pragma unroll
            for (int jp = 0; jp < 2; jp++)
                ldmx4(bf[jp], bT + jp * (16 * ROWB) + ks * 32);

            #pragma unroll
            for (int i = 0; i < 4; i++)
                #pragma unroll
                for (int j = 0; j < 4; j++) {
                    const uint32_t b0 = bf[j >> 1][(j & 1) * 2 + 0];
                    const uint32_t b1 = bf[j >> 1][(j & 1) * 2 + 1];
                    asm volatile(
                        "mma.sync.aligned.m16n8k32.row.col.s32.s8.s8.s32 "
                        "{%0,%1,%2,%3}, {%4,%5,%6,%7}, {%8,%9}, {%0,%1,%2,%3};\n"
                        : "+r"(acc[i][j][0]), "+r"(acc[i][j][1]),
                          "+r"(acc[i][j][2]), "+r"(acc[i][j][3])
                        : "r"(af[i][0]), "r"(af[i][1]),
                          "r"(af[i][2]), "r"(af[i][3]),
                          "r"(b0), "r"(b1));
                }
        }
        if (++st == NSTG) st = 0;
    }

    const int rbase = bm0 + wr * 64;
    float xx[4][2], sxr[4][2];
    int lab[4][2];
    #pragma unroll
    for (int i = 0; i < 4; i++)
        #pragma unroll
        for (int h = 0; h < 2; h++) {
            int row = rbase + i * 16 + g + h * 8;
            xx[i][h]  = g_xx[row];
            sxr[i][h] = g_sx[row];
            lab[i][h] = labels[row];
        }

    const int cbase = bn0 + wc * 32;
    #pragma unroll
    for (int j = 0; j < 4; j++) {
        int c0 = cbase + j * 8 + tg * 2;
        if (c0 < CC) {
            float yy0 = g_yy[c0],   yy1 = g_yy[c0 + 1];
            float sy0 = g_sy[c0],   sy1 = g_sy[c0 + 1];
            float v0  = g_var2[c0], v1  = g_var2[c0 + 1];
            #pragma unroll
            for (int i = 0; i < 4; i++)
                #pragma unroll
                for (int h = 0; h < 2; h++) {
                    int row = rbase + i * 16 + g + h * 8;
                    float xy0 = sxr[i][h] * sy0 * (float)acc[i][j][h * 2 + 0];
                    float xy1 = sxr[i][h] * sy1 * (float)acc[i][j][h * 2 + 1];
                    float l0 = -0.5f * (xx[i][h] - 2.0f * xy0 + yy0) * v0;
                    float l1 = -0.5f * (xx[i][h] - 2.0f * xy1 + yy1) * v1;
                    if (lab[i][h] == c0)     l0 *= 1.1f;
                    if (lab[i][h] == c0 + 1) l1 *= 1.1f;
                    float2 st2; st2.x = l0; st2.y = l1;
                    *(float2*)(out + (size_t)row * CC + c0) = st2;
                }
        }
    }
}

// ---------------------------------------------------------------------------
extern "C" void kernel_launch(void* const* d_in, const int* in_sizes, int n_in,
                              void* d_out, int out_size) {
    const float* feat     = (const float*)d_in[0];
    const int*   labels   = (const int*)d_in[1];     // int32 (JAX x64 disabled)
    const float* means    = (const float*)d_in[2];
    const float* variance = (const float*)d_in[3];
    float* out = (float*)d_out;

    const long long logitsN = (long long)BSZ * CC;      // 40,960,000
    const long long meansN  = (long long)CC * DD;       // 10,240,000
    long long osz = (long long)out_size;
    const int do_copy = (osz >= logitsN + 1 + meansN) ? 1 : 0;
    const int do_loss = (osz >= logitsN + 1) ? 1 : 0;

    cudaFuncSetAttribute(k_gemm, cudaFuncAttributeMaxDynamicSharedMemorySize,
                         SMEM_TOTAL);

    // Side streams/events (host-side resources; created once).
    // sCopy gets LOW priority so the big copy backfills around the GEMM
    // instead of flooding the work distributor ahead of it.
    static cudaStream_t sCopy = nullptr, sMeans = nullptr, sRed = nullptr;
    static cudaEvent_t eFork = nullptr, eFeat = nullptr, eMeans = nullptr,
                       eCopyD = nullptr, eRedD = nullptr;
    if (!sCopy) {
        int prLow = 0, prHigh = 0;
        cudaDeviceGetStreamPriorityRange(&prLow, &prHigh);
        cudaStreamCreateWithPriority(&sCopy, cudaStreamNonBlocking, prLow);
        cudaStreamCreateWithFlags(&sMeans, cudaStreamNonBlocking);
        cudaStreamCreateWithFlags(&sRed,   cudaStreamNonBlocking);
        cudaEventCreateWithFlags(&eFork,  cudaEventDisableTiming);
        cudaEventCreateWithFlags(&eFeat,  cudaEventDisableTiming);
        cudaEventCreateWithFlags(&eMeans, cudaEventDisableTiming);
        cudaEventCreateWithFlags(&eCopyD, cudaEventDisableTiming);
        cudaEventCreateWithFlags(&eRedD,  cudaEventDisableTiming);
    }

    // Fork point on the capture (default) stream.
    cudaEventRecord(eFork, 0);

    // prep_means on its own stream (concurrent with prep_feat).
    cudaStreamWaitEvent(sMeans, eFork, 0);
    k_prep_means<<<CC, 128, 0, sMeans>>>(means, variance);

    // Main stream: prep_feat.
    k_prep_feat_diff<<<BSZ, 128>>>(feat, labels, means);
    cudaEventRecord(eFeat, 0);

    // Loss reduce: needs prep_feat only; overlaps GEMM on side stream.
    if (do_loss) {
        cudaStreamWaitEvent(sRed, eFeat, 0);
        k_reduce<<<1, 1024, 0, sRed>>>(out + logitsN);
    }

    // GEMM (high on the default stream) -- issued BEFORE the copy so it owns
    // the work distributor; waits on prep_means too.
    cudaEventRecord(eMeans, sMeans);
    cudaStreamWaitEvent(0, eMeans, 0);

    dim3 grid((CC + BN - 1) / BN, BSZ / BM);   // 79 x 32
    k_gemm<<<grid, 256, SMEM_TOTAL>>>(labels, out);

    // Copy: low priority, few fat grid-stride CTAs, dependent only on fork.
    if (do_copy) {
        cudaStreamWaitEvent(sCopy, eFork, 0);
        k_copy<<<296, 1024, 0, sCopy>>>(means, out + logitsN + 1);
    }

    // Join side branches back into the capture stream.
    if (do_copy) { cudaEventRecord(eCopyD, sCopy); cudaStreamWaitEvent(0, eCopyD, 0); }
    if (do_loss) { cudaEventRecord(eRedD,  sRed);  cudaStreamWaitEvent(0, eRedD, 0); }
}